// round 10
// baseline (speedup 1.0000x reference)
#include <cuda_runtime.h>
#include <cuda_bf16.h>
#include <math.h>

#define BB 4
#define NA 50
#define SZ 256
#define SS (SZ*SZ)
#define NC 32
#define PP 512
#define CEN 127.5f
#define NZ 8

typedef unsigned long long u64;
typedef unsigned int u32;

// ---- packed f32x2 helpers ----
__device__ __forceinline__ u64 pk2(float lo, float hi) {
    u64 r; asm("mov.b64 %0, {%1, %2};" : "=l"(r) : "f"(lo), "f"(hi)); return r;
}
__device__ __forceinline__ u64 fma2(u64 a, u64 b, u64 c) {
    u64 d; asm("fma.rn.f32x2 %0, %1, %2, %3;" : "=l"(d) : "l"(a), "l"(b), "l"(c)); return d;
}
__device__ __forceinline__ void unpk2(u64 v, float& lo, float& hi) {
    asm("mov.b64 {%0, %1}, %2;" : "=f"(lo), "=f"(hi) : "l"(v));
}
__device__ __forceinline__ u32 smem_u32(const void* p) {
    u32 a;
    asm("{ .reg .u64 t; cvta.to.shared.u64 t, %1; cvt.u32.u64 %0, t; }" : "=r"(a) : "l"(p));
    return a;
}
// ---- generic tensor-core PTX (sm_80+ baseline; NO tcgen05) ----
__device__ __forceinline__ void ldsm4(u32& r0, u32& r1, u32& r2, u32& r3, u32 addr) {
    asm volatile("ldmatrix.sync.aligned.m8n8.x4.shared.b16 {%0,%1,%2,%3}, [%4];"
        : "=r"(r0), "=r"(r1), "=r"(r2), "=r"(r3) : "r"(addr));
}
__device__ __forceinline__ void mma_bf16(float* d, u32 a0, u32 a1, u32 a2, u32 a3,
                                         u32 b0, u32 b1) {
    asm volatile("mma.sync.aligned.m16n8k16.row.col.f32.bf16.bf16.f32 "
        "{%0,%1,%2,%3},{%4,%5,%6,%7},{%8,%9},{%0,%1,%2,%3};"
        : "+f"(d[0]), "+f"(d[1]), "+f"(d[2]), "+f"(d[3])
        : "r"(a0), "r"(a1), "r"(a2), "r"(a3), "r"(b0), "r"(b1));
}

// ---------------- scratch ----------------
__device__ float g_part[NZ*BB*NA*SZ];
__device__ float g_filt[BB*NA*SZ];
__device__ float g_h1[BB*NC*SS];
__device__ float g_h2[BB*NC*SS];
__device__ float g_up[BB*SS];
// pre-split weights: [split][oc][k], oc pitch 296 bf16 (592 B), k = ky*96+kx*32+ic
__device__ __align__(16) unsigned char g_wB2[2 * 32 * 296 * 2];   // 37,888 B

// ---------------- 1. radon forward: band-tiled, mask fused ----------------
__global__ void __launch_bounds__(256) k_radon(const float* __restrict__ yprev,
                                               const float* __restrict__ angles) {
    __shared__ float s_band[33][257];
    int a = blockIdx.x, b = blockIdx.y, z = blockIdx.z;
    int s = threadIdx.x;
    int y0 = z * 32;
    int lo = (z == 0) ? -1 : y0;
    int hi = y0 + 32;

    const float* im = &yprev[b * SS];
    float dxm = (float)s - CEN;
    #pragma unroll
    for (int i = 0; i < 33; ++i) {
        int gy = y0 + i;
        float dym = (float)gy - CEN;
        float m = (dym * dym + dxm * dxm <= 16384.0f) ? 1.0f : 0.0f;
        s_band[i][s] = (gy <= 255) ? im[gy * SZ + s] * m : 0.0f;
    }
    __syncthreads();

    float ca, sa;
    __sincosf(angles[a], &sa, &ca);
    float sf = (float)s - CEN;
    float rowA = sf * sa - CEN * ca + CEN;
    float colA = sf * ca + CEN * sa + CEN;

    float tmin, tmax;
    if (fabsf(ca) > 1e-6f) {
        float t1 = ((float)lo - 0.5f - rowA) / ca;
        float t2 = ((float)hi + 0.5f - rowA) / ca;
        tmin = fminf(t1, t2) - 1.0f;
        tmax = fmaxf(t1, t2) + 1.0f;
    } else {
        bool inb = (rowA >= (float)lo - 1.0f) && (rowA < (float)hi + 1.0f);
        tmin = inb ? 0.0f : 1.0f;
        tmax = inb ? 255.0f : 0.0f;
    }
    int ts = max(0, (int)floorf(tmin));
    int te = min(255, (int)ceilf(tmax));

    float sum = 0.0f;
    for (int t = ts; t <= te; ++t) {
        float row = rowA + (float)t * ca;
        float rf = floorf(row);
        int r0 = (int)rf;
        if (r0 < lo || r0 >= hi) continue;
        float wr = row - rf;
        float col = colA - (float)t * sa;
        float cf = floorf(col);
        int c0 = (int)cf;
        float wc = col - cf;
        int c0c = min(max(c0, 0), 255);
        int c1c = min(max(c0 + 1, 0), 255);
        float mc0 = (c0 == c0c) ? 1.0f : 0.0f;
        float mc1 = (c0 + 1 == c1c) ? 1.0f : 0.0f;
        float mr0 = (r0 >= 0) ? 1.0f : 0.0f;
        int lr = r0 - y0;
        int lrc = max(lr, 0);
        float v00 = s_band[lrc][c0c],     v01 = s_band[lrc][c1c];
        float v10 = s_band[lr + 1][c0c],  v11 = s_band[lr + 1][c1c];
        float top = mc0 * (1.0f - wc) * v00 + mc1 * wc * v01;
        float bot = mc0 * (1.0f - wc) * v10 + mc1 * wc * v11;
        sum += mr0 * (1.0f - wr) * top + wr * bot;
    }
    g_part[((z * BB + b) * NA + a) * SZ + s] = sum;
}

// ---------------- 2. ramp filter ----------------
__device__ __forceinline__ float hval(int m) {
    if (m == 0) return 0.5f;
    if ((m & 1) == 0) return 0.0f;
    float sv = sinf((float)M_PI * (float)m / (float)PP);
    return -2.0f / ((float)PP * (float)PP * sv * sv);
}
__global__ void k_filter(const float* __restrict__ x_sino) {
    __shared__ float sd[SZ];
    __shared__ float sh[PP];
    int a = blockIdx.x, b = blockIdx.y;
    int n = threadIdx.x;
    int base = (b * NA + a) * SZ + n;
    float d = -x_sino[base];
    #pragma unroll
    for (int z = 0; z < NZ; ++z) d += g_part[((z * BB + b) * NA + a) * SZ + n];
    sd[n] = d;
    sh[n] = hval(n);
    sh[n + 256] = hval(n + 256);
    __syncthreads();
    float acc = 0.5f * sd[n];
    int m0 = (n & 1) ^ 1;
    #pragma unroll 8
    for (int j = 0; j < 128; ++j) {
        int m = m0 + 2 * j;
        acc += sd[m] * sh[(n - m + PP) & (PP - 1)];
    }
    g_filt[base] = acc * (float)(M_PI / (2.0 * NA));
}

// ---------------- 3. backprojection + update ----------------
__global__ void __launch_bounds__(512) k_backproj(const float* __restrict__ yprev,
                                                  const float* __restrict__ angles,
                                                  const float* __restrict__ step,
                                                  float* __restrict__ out_up) {
    __shared__ float s_sino[25 * SZ];
    __shared__ float s_cos[NA], s_sin[NA];
    int b = blockIdx.y;
    int tid = threadIdx.x;
    int j = tid & 255, half = tid >> 8;
    int i = blockIdx.x * 2 + half;
    if (tid < NA) { s_cos[tid] = cosf(angles[tid]); s_sin[tid] = sinf(angles[tid]); }
    __syncthreads();
    float xx = (float)j - CEN, yy = (float)i - CEN;
    float acc = 0.0f;
    for (int ch = 0; ch < 2; ++ch) {
        for (int k = tid; k < 25 * SZ; k += 512) {
            s_sino[k] = g_filt[(b * NA + ch * 25) * SZ + k];
        }
        __syncthreads();
        #pragma unroll 5
        for (int al = 0; al < 25; ++al) {
            int a = ch * 25 + al;
            float det = xx * s_cos[a] + yy * s_sin[a] + CEN;
            float df = floorf(det);
            int i0 = (int)df;
            i0 = i0 < 0 ? 0 : (i0 > SZ - 2 ? SZ - 2 : i0);
            float w = det - (float)i0;
            float v = s_sino[al * SZ + i0] * (1.0f - w) + s_sino[al * SZ + i0 + 1] * w;
            if (det >= 0.0f && det <= (float)(SZ - 1)) acc += v;
        }
        __syncthreads();
    }
    float m = (xx*xx + yy*yy <= 16384.0f) ? 1.0f : 0.0f;
    int o = b * SS + i * SZ + j;
    out_up[o] = yprev[o] + step[0] * (acc * m);
}

// ---------------- 4. conv1: 2 -> 32 tiled f32x2 (R8 proven) ----------------
#define RW 36
__global__ void __launch_bounds__(256) k_conv1(const float* __restrict__ yup,
                                               const float* __restrict__ ycat,
                                               const float* __restrict__ w1,
                                               const float* __restrict__ b1) {
    __shared__ __align__(16) float s_w2[18 * 32];
    __shared__ float s_b[NC];
    __shared__ __align__(16) float s_in0[10 * RW];
    __shared__ __align__(16) float s_in1[10 * RW];
    int tid = threadIdx.x;
    int b = blockIdx.z;
    int gx0 = blockIdx.x * 32 - 1;
    int gy0 = blockIdx.y * 8 - 1;
    for (int idx = tid; idx < 18 * 32; idx += 256) {
        int kk = idx >> 5, oc = idx & 31;
        s_w2[idx] = w1[oc * 18 + kk];
    }
    if (tid < NC) s_b[tid] = b1[tid];
    for (int idx = tid; idx < 10 * RW; idx += 256) {
        int rr = idx / RW, ccx = idx % RW;
        int gy = gy0 + rr, gx = gx0 + ccx;
        bool ok = (ccx < 34) && (gy >= 0) && (gy < SZ) && (gx >= 0) && (gx < SZ);
        int gi = b * SS + gy * SZ + gx;
        s_in0[idx] = ok ? yup[gi]  : 0.0f;
        s_in1[idx] = ok ? ycat[gi] : 0.0f;
    }
    __syncthreads();

    int q = tid & 7, r = (tid >> 3) & 7, og = tid >> 6;
    u64 acc2[4][4];
    #pragma unroll
    for (int op = 0; op < 4; ++op) {
        int oc0 = og * 8 + 2 * op;
        u64 bp = pk2(s_b[oc0], s_b[oc0 + 1]);
        #pragma unroll
        for (int p = 0; p < 4; ++p) acc2[op][p] = bp;
    }
    #pragma unroll
    for (int ic = 0; ic < 2; ++ic) {
        const float* inb = ic ? s_in1 : s_in0;
        const float* wb  = &s_w2[ic * 288];
        #pragma unroll
        for (int ky = 0; ky < 3; ++ky) {
            const float* rowp = inb + (r + ky) * RW + q * 4;
            float4 va = *(const float4*)rowp;
            float2 vb = *(const float2*)(rowp + 4);
            float ivf[6] = {va.x, va.y, va.z, va.w, vb.x, vb.y};
            u64 ivp[6];
            #pragma unroll
            for (int m = 0; m < 6; ++m) ivp[m] = pk2(ivf[m], ivf[m]);
            #pragma unroll
            for (int kx = 0; kx < 3; ++kx) {
                const ulonglong2 wv0 = *(const ulonglong2*)&wb[(ky*3+kx)*32 + og*8];
                const ulonglong2 wv1 = *(const ulonglong2*)&wb[(ky*3+kx)*32 + og*8 + 4];
                u64 wp[4] = {wv0.x, wv0.y, wv1.x, wv1.y};
                #pragma unroll
                for (int op = 0; op < 4; ++op)
                    #pragma unroll
                    for (int p = 0; p < 4; ++p)
                        acc2[op][p] = fma2(wp[op], ivp[kx + p], acc2[op][p]);
            }
        }
    }
    int gy = blockIdx.y * 8 + r;
    int gxb = blockIdx.x * 32 + q * 4;
    #pragma unroll
    for (int op = 0; op < 4; ++op) {
        int oc0 = og * 8 + 2 * op;
        float l0,h0,l1,h1,l2,h2,l3,h3;
        unpk2(acc2[op][0], l0, h0); unpk2(acc2[op][1], l1, h1);
        unpk2(acc2[op][2], l2, h2); unpk2(acc2[op][3], l3, h3);
        float4 vlo = make_float4(fmaxf(l0,0.f), fmaxf(l1,0.f), fmaxf(l2,0.f), fmaxf(l3,0.f));
        float4 vhi = make_float4(fmaxf(h0,0.f), fmaxf(h1,0.f), fmaxf(h2,0.f), fmaxf(h3,0.f));
        *(float4*)&g_h1[((b * NC + oc0)     << 16) + gy * SZ + gxb] = vlo;
        *(float4*)&g_h1[((b * NC + oc0 + 1) << 16) + gy * SZ + gxb] = vhi;
    }
}

// ---------------- 5a. weight prep: split bf16 into [split][oc][k] ----------
__global__ void k_prepw(const float* __restrict__ w2) {
    int tid = threadIdx.x;
    for (int idx = tid; idx < 2 * 32 * 296; idx += 256) {
        int split = idx / (32 * 296);
        int rem = idx % (32 * 296);
        int oc = rem / 296;
        int k = rem % 296;
        unsigned short bits = 0;
        if (k < 288) {
            int ky = k / 96, r2 = k % 96, kx = r2 / 32, ic = r2 % 32;
            float v = w2[oc * 288 + ic * 9 + ky * 3 + kx];
            u32 u = __float_as_uint(v);
            if (split == 0) {
                bits = (unsigned short)(u >> 16);                       // truncated hi
            } else {
                float lo = v - __uint_as_float(u & 0xffff0000u);        // exact residual
                bits = __bfloat16_as_ushort(__float2bfloat16(lo));
            }
        }
        *(unsigned short*)(g_wB2 + idx * 2) = bits;
    }
}

// ---------------- 5b. conv2: mma.sync bf16 split-precision implicit GEMM ---
// grid (2, 256, BB), 128 thr. CTA: 128 px of one row x 32 oc.
// A[px][k], k = ky*96+kx*32+ic; hi/lo planes. D += over 3 combos x 3ky x 6 k-tiles.
#define CV2_A_LO 31680                 // bytes: 396 rows x 80 B
#define CV2_W    63360
#define CV2_WSPLIT 18944               // 32 oc x 592 B
#define CV2_SMEM (CV2_W + 37888)       // 101,248 B
__global__ void __launch_bounds__(128) k_conv2(const float* __restrict__ b2) {
    extern __shared__ __align__(1024) unsigned char smem_dyn[];
    __shared__ float s_bias[NC];
    int tid = threadIdx.x;
    int b = blockIdx.z, gy = blockIdx.y, gx0 = blockIdx.x * 128;
    u32 dyn = smem_u32(smem_dyn);
    if (tid < NC) s_bias[tid] = b2[tid];

    // stage pre-split weights (37,888 B)
    {
        const uint4* src = (const uint4*)g_wB2;
        uint4* dst = (uint4*)(smem_dyn + CV2_W);
        for (int i = tid; i < 37888 / 16; i += 128) dst[i] = src[i];
    }
    // stage input rows gy-1..gy+1, px gx0-1..gx0+128, as bf16x2 hi/lo planes
    u32* s_hi = (u32*)smem_dyn;
    u32* s_lo = (u32*)(smem_dyn + CV2_A_LO);
    for (int idx = tid; idx < 3 * 16 * 130; idx += 128) {
        int rr = idx / (16 * 130);
        int rem = idx % (16 * 130);
        int ic2 = rem / 130;
        int px = rem % 130;
        int gyy = gy + rr - 1, gxx = gx0 + px - 1;
        bool ok = (gyy >= 0) && (gyy < SZ) && (gxx >= 0) && (gxx < SZ);
        float v0 = 0.0f, v1 = 0.0f;
        if (ok) {
            v0 = g_h1[((b * NC + 2 * ic2)     << 16) + gyy * SZ + gxx];
            v1 = g_h1[((b * NC + 2 * ic2 + 1) << 16) + gyy * SZ + gxx];
        }
        u32 u0 = __float_as_uint(v0), u1 = __float_as_uint(v1);
        u32 hp = (u0 >> 16) | (u1 & 0xffff0000u);
        float l0 = v0 - __uint_as_float(u0 & 0xffff0000u);
        float l1 = v1 - __uint_as_float(u1 & 0xffff0000u);
        u32 lp = (u32)__bfloat16_as_ushort(__float2bfloat16(l0))
               | ((u32)__bfloat16_as_ushort(__float2bfloat16(l1)) << 16);
        int so = (rr * 132 + px) * 20 + ic2;   // row pitch 40 bf16 = 20 u32 (conflict-free)
        s_hi[so] = hp;
        s_lo[so] = lp;
    }
    __syncthreads();

    int warp = tid >> 5, lane = tid & 31;
    float d[2][4][4];
    #pragma unroll
    for (int mt = 0; mt < 2; ++mt)
        #pragma unroll
        for (int nt = 0; nt < 4; ++nt)
            #pragma unroll
            for (int rr = 0; rr < 4; ++rr) d[mt][nt][rr] = 0.0f;

    u32 a_lane = (u32)(((lane & 7) + ((lane >> 3) & 1) * 8) * 80 + (lane >> 4) * 16);
    u32 b_row  = (u32)((lane >> 4) * 8 + (lane & 7));
    u32 b_koff = (u32)(((lane >> 3) & 1) * 16);

    #pragma unroll
    for (int c = 0; c < 3; ++c) {
        u32 abase = dyn + (c == 2 ? CV2_A_LO : 0);
        u32 wbase = dyn + CV2_W + (c == 1 ? CV2_WSPLIT : 0);
        #pragma unroll
        for (int ky = 0; ky < 3; ++ky) {
            #pragma unroll
            for (int kt = 0; kt < 6; ++kt) {
                int kx = kt >> 1, ic0 = (kt & 1) * 16;
                u32 arow = abase + (u32)((ky * 132 + warp * 32 + kx) * 80 + ic0 * 2) + a_lane;
                u32 a0,a1,a2,a3,a4,a5,a6,a7;
                ldsm4(a0, a1, a2, a3, arow);
                ldsm4(a4, a5, a6, a7, arow + 16 * 80);
                u32 kb = (u32)((ky * 96 + kt * 16) * 2) + b_koff;
                u32 b0,b1,b2,b3,b4,b5,b6,b7;
                ldsm4(b0, b1, b2, b3, wbase + b_row * 592 + kb);
                ldsm4(b4, b5, b6, b7, wbase + (b_row + 16) * 592 + kb);
                mma_bf16(d[0][0], a0,a1,a2,a3, b0,b1);
                mma_bf16(d[0][1], a0,a1,a2,a3, b2,b3);
                mma_bf16(d[0][2], a0,a1,a2,a3, b4,b5);
                mma_bf16(d[0][3], a0,a1,a2,a3, b6,b7);
                mma_bf16(d[1][0], a4,a5,a6,a7, b0,b1);
                mma_bf16(d[1][1], a4,a5,a6,a7, b2,b3);
                mma_bf16(d[1][2], a4,a5,a6,a7, b4,b5);
                mma_bf16(d[1][3], a4,a5,a6,a7, b6,b7);
            }
        }
    }
    __syncthreads();

    // epilogue: bias + relu, transpose via smem (overlay weight region)
    float* s_out = (float*)(smem_dyn + CV2_W);
    #pragma unroll
    for (int mt = 0; mt < 2; ++mt) {
        int px = warp * 32 + mt * 16 + (lane >> 2);
        #pragma unroll
        for (int nt = 0; nt < 4; ++nt) {
            int oc = nt * 8 + (lane & 3) * 2;
            s_out[oc * 128 + px]           = fmaxf(d[mt][nt][0] + s_bias[oc],     0.0f);
            s_out[(oc + 1) * 128 + px]     = fmaxf(d[mt][nt][1] + s_bias[oc + 1], 0.0f);
            s_out[oc * 128 + px + 8]       = fmaxf(d[mt][nt][2] + s_bias[oc],     0.0f);
            s_out[(oc + 1) * 128 + px + 8] = fmaxf(d[mt][nt][3] + s_bias[oc + 1], 0.0f);
        }
    }
    __syncthreads();
    for (int idx = tid; idx < NC * 128; idx += 128) {
        int c = idx >> 7, px = idx & 127;
        g_h2[((b * NC + c) << 16) + gy * SZ + gx0 + px] = s_out[idx];
    }
}

// ---------------- 6. conv3: 32 -> 1, smem-chunked (R8 proven) --------------
__global__ void __launch_bounds__(256) k_conv3(const float* __restrict__ w3,
                                               const float* __restrict__ b3,
                                               float* __restrict__ out_img) {
    __shared__ float s_w[NC * 9];
    __shared__ __align__(16) float s_in[8 * 10 * RW];
    int tid = threadIdx.x;
    int b = blockIdx.z;
    int gx0 = blockIdx.x * 32 - 1;
    int gy0 = blockIdx.y * 8 - 1;
    for (int k = tid; k < NC * 9; k += 256) s_w[k] = w3[k];

    int jl = tid & 31, il = tid >> 5;
    float acc = b3[0];
    for (int cc = 0; cc < 4; ++cc) {
        __syncthreads();
        for (int idx = tid; idx < 8 * 10 * RW; idx += 256) {
            int ic = idx / (10 * RW), rem = idx % (10 * RW);
            int rr = rem / RW, ccx = rem % RW;
            int gy = gy0 + rr, gx = gx0 + ccx;
            bool ok = (ccx < 34) && (gy >= 0) && (gy < SZ) && (gx >= 0) && (gx < SZ);
            s_in[idx] = ok ? g_h2[((b * NC + cc * 8 + ic) << 16) + gy * SZ + gx] : 0.0f;
        }
        __syncthreads();
        #pragma unroll
        for (int ic = 0; ic < 8; ++ic) {
            const float* inb = &s_in[ic * 10 * RW];
            const float* w = &s_w[(cc * 8 + ic) * 9];
            #pragma unroll
            for (int ky = 0; ky < 3; ++ky) {
                const float* rowp = inb + (il + ky) * RW + jl;
                acc += rowp[0] * w[ky*3] + rowp[1] * w[ky*3+1] + rowp[2] * w[ky*3+2];
            }
        }
    }
    int gy = blockIdx.y * 8 + il;
    int gx = blockIdx.x * 32 + jl;
    out_img[b * SS + gy * SZ + gx] = acc;
}

// ---------------- launch ----------------
extern "C" void kernel_launch(void* const* d_in, const int* in_sizes, int n_in,
                              void* d_out, int out_size) {
    const float *x_sino = 0, *y_prev = 0, *y_cat = 0, *angles = 0, *step = 0;
    const float *w1 = 0, *b1 = 0, *w2 = 0, *b2 = 0, *w3 = 0, *b3 = 0;

    int ix = -1;
    for (int i = 0; i < n_in; ++i) if (in_sizes[i] == 51200) ix = i;
    bool dict_order = (ix == 0);

    int n262 = 0, n32 = 0, n1 = 0;
    for (int i = 0; i < n_in; ++i) {
        const float* p = (const float*)d_in[i];
        switch (in_sizes[i]) {
            case 51200: x_sino = p; break;
            case 50:    angles = p; break;
            case 576:   w1 = p; break;
            case 9216:  w2 = p; break;
            case 288:   w3 = p; break;
            case 262144:
                if (dict_order) { if (n262 == 0) y_prev = p; else y_cat = p; }
                else            { if (n262 == 0) y_cat  = p; else y_prev = p; }
                ++n262; break;
            case 32:
                if (n32 == 0) b1 = p; else b2 = p;
                ++n32; break;
            case 1:
                if (dict_order) { if (n1 == 0) step = p; else b3 = p; }
                else            { if (n1 == 0) b3   = p; else step = p; }
                ++n1; break;
            default: break;
        }
    }

    float* out_img = (float*)d_out;
    float* out_up;
    if (out_size >= 2 * BB * SS) {
        out_up = (float*)d_out + BB * SS;
    } else {
        cudaGetSymbolAddress((void**)&out_up, g_up);
    }

    cudaFuncSetAttribute(k_conv2, cudaFuncAttributeMaxDynamicSharedMemorySize, CV2_SMEM);

    k_prepw<<<1, 256>>>(w2);
    k_radon<<<dim3(NA, BB, NZ), 256>>>(y_prev, angles);
    k_filter<<<dim3(NA, BB), 256>>>(x_sino);
    k_backproj<<<dim3(SZ / 2, BB), 512>>>(y_prev, angles, step, out_up);
    k_conv1<<<dim3(8, 32, BB), 256>>>(out_up, y_cat, w1, b1);
    k_conv2<<<dim3(2, SZ, BB), 128, CV2_SMEM>>>(b2);
    k_conv3<<<dim3(8, 32, BB), 256>>>(w3, b3, out_img);
}

// round 11
// speedup vs baseline: 1.1539x; 1.1539x over previous
#include <cuda_runtime.h>
#include <math.h>

#define BB 4
#define NA 50
#define SZ 256
#define SS (SZ*SZ)
#define NC 32
#define PP 512
#define CEN 127.5f
#define NZ 8

typedef unsigned long long u64;

// ---- packed f32x2 helpers (sm_103a dual-rate fp32 path) ----
__device__ __forceinline__ u64 pk2(float lo, float hi) {
    u64 r; asm("mov.b64 %0, {%1, %2};" : "=l"(r) : "f"(lo), "f"(hi)); return r;
}
__device__ __forceinline__ u64 fma2(u64 a, u64 b, u64 c) {
    u64 d; asm("fma.rn.f32x2 %0, %1, %2, %3;" : "=l"(d) : "l"(a), "l"(b), "l"(c)); return d;
}
__device__ __forceinline__ void unpk2(u64 v, float& lo, float& hi) {
    asm("mov.b64 {%0, %1}, %2;" : "=f"(lo), "=f"(hi) : "l"(v));
}

// ---------------- scratch ----------------
__device__ float g_part[NZ*BB*NA*SZ];
__device__ float g_filt[BB*NA*SZ];
__device__ float g_h1[BB*NC*SS];
__device__ float g_h2[BB*NC*SS];
__device__ float g_up[BB*SS];

// ---------------- 1. radon forward: band-tiled, mask fused ----------------
__global__ void __launch_bounds__(256) k_radon(const float* __restrict__ yprev,
                                               const float* __restrict__ angles) {
    __shared__ float s_band[33][257];
    int a = blockIdx.x, b = blockIdx.y, z = blockIdx.z;
    int s = threadIdx.x;
    int y0 = z * 32;
    int lo = (z == 0) ? -1 : y0;
    int hi = y0 + 32;

    const float* im = &yprev[b * SS];
    float dxm = (float)s - CEN;
    #pragma unroll
    for (int i = 0; i < 33; ++i) {
        int gy = y0 + i;
        float dym = (float)gy - CEN;
        float m = (dym * dym + dxm * dxm <= 16384.0f) ? 1.0f : 0.0f;
        s_band[i][s] = (gy <= 255) ? im[gy * SZ + s] * m : 0.0f;
    }
    __syncthreads();

    float ca, sa;
    __sincosf(angles[a], &sa, &ca);
    float sf = (float)s - CEN;
    float rowA = sf * sa - CEN * ca + CEN;
    float colA = sf * ca + CEN * sa + CEN;

    float tmin, tmax;
    if (fabsf(ca) > 1e-6f) {
        float t1 = ((float)lo - 0.5f - rowA) / ca;
        float t2 = ((float)hi + 0.5f - rowA) / ca;
        tmin = fminf(t1, t2) - 1.0f;
        tmax = fmaxf(t1, t2) + 1.0f;
    } else {
        bool inb = (rowA >= (float)lo - 1.0f) && (rowA < (float)hi + 1.0f);
        tmin = inb ? 0.0f : 1.0f;
        tmax = inb ? 255.0f : 0.0f;
    }
    int ts = max(0, (int)floorf(tmin));
    int te = min(255, (int)ceilf(tmax));

    float sum = 0.0f;
    for (int t = ts; t <= te; ++t) {
        float row = rowA + (float)t * ca;
        float rf = floorf(row);
        int r0 = (int)rf;
        if (r0 < lo || r0 >= hi) continue;
        float wr = row - rf;
        float col = colA - (float)t * sa;
        float cf = floorf(col);
        int c0 = (int)cf;
        float wc = col - cf;
        int c0c = min(max(c0, 0), 255);
        int c1c = min(max(c0 + 1, 0), 255);
        float mc0 = (c0 == c0c) ? 1.0f : 0.0f;
        float mc1 = (c0 + 1 == c1c) ? 1.0f : 0.0f;
        float mr0 = (r0 >= 0) ? 1.0f : 0.0f;
        int lr = r0 - y0;
        int lrc = max(lr, 0);
        float v00 = s_band[lrc][c0c],     v01 = s_band[lrc][c1c];
        float v10 = s_band[lr + 1][c0c],  v11 = s_band[lr + 1][c1c];
        float top = mc0 * (1.0f - wc) * v00 + mc1 * wc * v01;
        float bot = mc0 * (1.0f - wc) * v10 + mc1 * wc * v11;
        sum += mr0 * (1.0f - wr) * top + wr * bot;
    }
    g_part[((z * BB + b) * NA + a) * SZ + s] = sum;
}

// ---------------- 2. ramp filter ----------------
__device__ __forceinline__ float hval(int m) {
    if (m == 0) return 0.5f;
    if ((m & 1) == 0) return 0.0f;
    float sv = sinf((float)M_PI * (float)m / (float)PP);
    return -2.0f / ((float)PP * (float)PP * sv * sv);
}
__global__ void k_filter(const float* __restrict__ x_sino) {
    __shared__ float sd[SZ];
    __shared__ float sh[PP];
    int a = blockIdx.x, b = blockIdx.y;
    int n = threadIdx.x;
    int base = (b * NA + a) * SZ + n;
    float d = -x_sino[base];
    #pragma unroll
    for (int z = 0; z < NZ; ++z) d += g_part[((z * BB + b) * NA + a) * SZ + n];
    sd[n] = d;
    sh[n] = hval(n);
    sh[n + 256] = hval(n + 256);
    __syncthreads();
    float acc = 0.5f * sd[n];
    int m0 = (n & 1) ^ 1;
    #pragma unroll 8
    for (int j = 0; j < 128; ++j) {
        int m = m0 + 2 * j;
        acc += sd[m] * sh[(n - m + PP) & (PP - 1)];
    }
    g_filt[base] = acc * (float)(M_PI / (2.0 * NA));
}

// ---------------- 3. backprojection + update (4 rows/block, 1024 thr) ------
__global__ void __launch_bounds__(1024) k_backproj(const float* __restrict__ yprev,
                                                   const float* __restrict__ angles,
                                                   const float* __restrict__ step,
                                                   float* __restrict__ out_up) {
    __shared__ float s_sino[25 * SZ];
    __shared__ float s_cos[NA], s_sin[NA];
    int b = blockIdx.y;
    int tid = threadIdx.x;
    int j = tid & 255, quart = tid >> 8;
    int i = blockIdx.x * 4 + quart;
    if (tid < NA) { s_cos[tid] = cosf(angles[tid]); s_sin[tid] = sinf(angles[tid]); }
    __syncthreads();
    float xx = (float)j - CEN, yy = (float)i - CEN;
    float acc = 0.0f;
    for (int ch = 0; ch < 2; ++ch) {
        for (int k = tid; k < 25 * SZ; k += 1024) {
            s_sino[k] = g_filt[(b * NA + ch * 25) * SZ + k];
        }
        __syncthreads();
        #pragma unroll 5
        for (int al = 0; al < 25; ++al) {
            int a = ch * 25 + al;
            float det = xx * s_cos[a] + yy * s_sin[a] + CEN;
            float df = floorf(det);
            int i0 = (int)df;
            i0 = i0 < 0 ? 0 : (i0 > SZ - 2 ? SZ - 2 : i0);
            float w = det - (float)i0;
            float v = s_sino[al * SZ + i0] * (1.0f - w) + s_sino[al * SZ + i0 + 1] * w;
            if (det >= 0.0f && det <= (float)(SZ - 1)) acc += v;
        }
        __syncthreads();
    }
    float m = (xx*xx + yy*yy <= 16384.0f) ? 1.0f : 0.0f;
    int o = b * SS + i * SZ + j;
    out_up[o] = yprev[o] + step[0] * (acc * m);
}

// ---------------- 4. conv1: 2 -> 32 tiled f32x2 (R8 proven) ----------------
#define RW 36
__global__ void __launch_bounds__(256) k_conv1(const float* __restrict__ yup,
                                               const float* __restrict__ ycat,
                                               const float* __restrict__ w1,
                                               const float* __restrict__ b1) {
    __shared__ __align__(16) float s_w2[18 * 32];
    __shared__ float s_b[NC];
    __shared__ __align__(16) float s_in0[10 * RW];
    __shared__ __align__(16) float s_in1[10 * RW];
    int tid = threadIdx.x;
    int b = blockIdx.z;
    int gx0 = blockIdx.x * 32 - 1;
    int gy0 = blockIdx.y * 8 - 1;
    for (int idx = tid; idx < 18 * 32; idx += 256) {
        int kk = idx >> 5, oc = idx & 31;
        s_w2[idx] = w1[oc * 18 + kk];
    }
    if (tid < NC) s_b[tid] = b1[tid];
    for (int idx = tid; idx < 10 * RW; idx += 256) {
        int rr = idx / RW, ccx = idx % RW;
        int gy = gy0 + rr, gx = gx0 + ccx;
        bool ok = (ccx < 34) && (gy >= 0) && (gy < SZ) && (gx >= 0) && (gx < SZ);
        int gi = b * SS + gy * SZ + gx;
        s_in0[idx] = ok ? yup[gi]  : 0.0f;
        s_in1[idx] = ok ? ycat[gi] : 0.0f;
    }
    __syncthreads();

    int q = tid & 7, r = (tid >> 3) & 7, og = tid >> 6;
    u64 acc2[4][4];
    #pragma unroll
    for (int op = 0; op < 4; ++op) {
        int oc0 = og * 8 + 2 * op;
        u64 bp = pk2(s_b[oc0], s_b[oc0 + 1]);
        #pragma unroll
        for (int p = 0; p < 4; ++p) acc2[op][p] = bp;
    }
    #pragma unroll
    for (int ic = 0; ic < 2; ++ic) {
        const float* inb = ic ? s_in1 : s_in0;
        const float* wb  = &s_w2[ic * 288];
        #pragma unroll
        for (int ky = 0; ky < 3; ++ky) {
            const float* rowp = inb + (r + ky) * RW + q * 4;
            float4 va = *(const float4*)rowp;
            float2 vb = *(const float2*)(rowp + 4);
            float ivf[6] = {va.x, va.y, va.z, va.w, vb.x, vb.y};
            u64 ivp[6];
            #pragma unroll
            for (int m = 0; m < 6; ++m) ivp[m] = pk2(ivf[m], ivf[m]);
            #pragma unroll
            for (int kx = 0; kx < 3; ++kx) {
                const ulonglong2 wv0 = *(const ulonglong2*)&wb[(ky*3+kx)*32 + og*8];
                const ulonglong2 wv1 = *(const ulonglong2*)&wb[(ky*3+kx)*32 + og*8 + 4];
                u64 wp[4] = {wv0.x, wv0.y, wv1.x, wv1.y};
                #pragma unroll
                for (int op = 0; op < 4; ++op)
                    #pragma unroll
                    for (int p = 0; p < 4; ++p)
                        acc2[op][p] = fma2(wp[op], ivp[kx + p], acc2[op][p]);
            }
        }
    }
    int gy = blockIdx.y * 8 + r;
    int gxb = blockIdx.x * 32 + q * 4;
    #pragma unroll
    for (int op = 0; op < 4; ++op) {
        int oc0 = og * 8 + 2 * op;
        float l0,h0,l1,h1,l2,h2,l3,h3;
        unpk2(acc2[op][0], l0, h0); unpk2(acc2[op][1], l1, h1);
        unpk2(acc2[op][2], l2, h2); unpk2(acc2[op][3], l3, h3);
        float4 vlo = make_float4(fmaxf(l0,0.f), fmaxf(l1,0.f), fmaxf(l2,0.f), fmaxf(l3,0.f));
        float4 vhi = make_float4(fmaxf(h0,0.f), fmaxf(h1,0.f), fmaxf(h2,0.f), fmaxf(h3,0.f));
        *(float4*)&g_h1[((b * NC + oc0)     << 16) + gy * SZ + gxb] = vlo;
        *(float4*)&g_h1[((b * NC + oc0 + 1) << 16) + gy * SZ + gxb] = vhi;
    }
}

// ---------------- 5. conv2: 32 -> 32 f32x2 (R8 proven config) --------------
#define ICH 16
__global__ void __launch_bounds__(256) k_conv2(const float* __restrict__ w2,
                                               const float* __restrict__ b2) {
    __shared__ __align__(16) float s_w[ICH * 9 * 32];   // [ic][k][oc]
    __shared__ __align__(16) float s_in[ICH * 10 * RW]; // [ic][row][col]
    __shared__ float s_b[NC];
    int tid = threadIdx.x;
    int q = tid & 7, r = (tid >> 3) & 7, og = tid >> 6;
    int b = blockIdx.z;
    int gx0 = blockIdx.x * 32 - 1;
    int gy0 = blockIdx.y * 8 - 1;
    if (tid < NC) s_b[tid] = b2[tid];

    u64 acc2[4][4];
    #pragma unroll
    for (int op = 0; op < 4; ++op)
        #pragma unroll
        for (int p = 0; p < 4; ++p) acc2[op][p] = 0ULL;

    for (int cc = 0; cc < 2; ++cc) {
        int icb = cc * ICH;
        __syncthreads();
        for (int idx = tid; idx < ICH * 288; idx += 256) {
            int ic = idx / 288, rem = idx % 288;
            int k = rem >> 5, oc = rem & 31;
            s_w[idx] = w2[oc * 288 + (icb + ic) * 9 + k];
        }
        for (int idx = tid; idx < ICH * 10 * RW; idx += 256) {
            int ic = idx / (10 * RW), rem = idx % (10 * RW);
            int rr = rem / RW, ccx = rem % RW;
            int gy = gy0 + rr, gx = gx0 + ccx;
            bool ok = (ccx < 34) && (gy >= 0) && (gy < SZ) && (gx >= 0) && (gx < SZ);
            s_in[idx] = ok ? g_h1[((b * NC + icb + ic) << 16) + gy * SZ + gx] : 0.0f;
        }
        __syncthreads();

        for (int ic = 0; ic < ICH; ++ic) {
            const float* inb = &s_in[ic * 10 * RW];
            const float* wb  = &s_w[ic * 288];
            #pragma unroll
            for (int ky = 0; ky < 3; ++ky) {
                const float* rowp = inb + (r + ky) * RW + q * 4;
                float4 va = *(const float4*)rowp;
                float2 vb = *(const float2*)(rowp + 4);
                float ivf[6] = {va.x, va.y, va.z, va.w, vb.x, vb.y};
                u64 ivp[6];
                #pragma unroll
                for (int m = 0; m < 6; ++m) ivp[m] = pk2(ivf[m], ivf[m]);
                #pragma unroll
                for (int kx = 0; kx < 3; ++kx) {
                    const ulonglong2 wv0 = *(const ulonglong2*)&wb[(ky*3+kx)*32 + og*8];
                    const ulonglong2 wv1 = *(const ulonglong2*)&wb[(ky*3+kx)*32 + og*8 + 4];
                    u64 wp[4] = {wv0.x, wv0.y, wv1.x, wv1.y};
                    #pragma unroll
                    for (int op = 0; op < 4; ++op)
                        #pragma unroll
                        for (int p = 0; p < 4; ++p)
                            acc2[op][p] = fma2(wp[op], ivp[kx + p], acc2[op][p]);
                }
            }
        }
    }
    int gy = blockIdx.y * 8 + r;
    int gxb = blockIdx.x * 32 + q * 4;
    #pragma unroll
    for (int op = 0; op < 4; ++op) {
        int oc0 = og * 8 + 2 * op;
        float blo = s_b[oc0], bhi = s_b[oc0 + 1];
        float l0,h0,l1,h1,l2,h2,l3,h3;
        unpk2(acc2[op][0], l0, h0); unpk2(acc2[op][1], l1, h1);
        unpk2(acc2[op][2], l2, h2); unpk2(acc2[op][3], l3, h3);
        float4 vlo = make_float4(fmaxf(l0+blo,0.f), fmaxf(l1+blo,0.f),
                                 fmaxf(l2+blo,0.f), fmaxf(l3+blo,0.f));
        float4 vhi = make_float4(fmaxf(h0+bhi,0.f), fmaxf(h1+bhi,0.f),
                                 fmaxf(h2+bhi,0.f), fmaxf(h3+bhi,0.f));
        *(float4*)&g_h2[((b * NC + oc0)     << 16) + gy * SZ + gxb] = vlo;
        *(float4*)&g_h2[((b * NC + oc0 + 1) << 16) + gy * SZ + gxb] = vhi;
    }
}

// ---------------- 6. conv3: 32 -> 1, smem-chunked (R8 proven) --------------
__global__ void __launch_bounds__(256) k_conv3(const float* __restrict__ w3,
                                               const float* __restrict__ b3,
                                               float* __restrict__ out_img) {
    __shared__ float s_w[NC * 9];
    __shared__ __align__(16) float s_in[8 * 10 * RW];
    int tid = threadIdx.x;
    int b = blockIdx.z;
    int gx0 = blockIdx.x * 32 - 1;
    int gy0 = blockIdx.y * 8 - 1;
    for (int k = tid; k < NC * 9; k += 256) s_w[k] = w3[k];

    int jl = tid & 31, il = tid >> 5;
    float acc = b3[0];
    for (int cc = 0; cc < 4; ++cc) {
        __syncthreads();
        for (int idx = tid; idx < 8 * 10 * RW; idx += 256) {
            int ic = idx / (10 * RW), rem = idx % (10 * RW);
            int rr = rem / RW, ccx = rem % RW;
            int gy = gy0 + rr, gx = gx0 + ccx;
            bool ok = (ccx < 34) && (gy >= 0) && (gy < SZ) && (gx >= 0) && (gx < SZ);
            s_in[idx] = ok ? g_h2[((b * NC + cc * 8 + ic) << 16) + gy * SZ + gx] : 0.0f;
        }
        __syncthreads();
        #pragma unroll
        for (int ic = 0; ic < 8; ++ic) {
            const float* inb = &s_in[ic * 10 * RW];
            const float* w = &s_w[(cc * 8 + ic) * 9];
            #pragma unroll
            for (int ky = 0; ky < 3; ++ky) {
                const float* rowp = inb + (il + ky) * RW + jl;
                acc += rowp[0] * w[ky*3] + rowp[1] * w[ky*3+1] + rowp[2] * w[ky*3+2];
            }
        }
    }
    int gy = blockIdx.y * 8 + il;
    int gx = blockIdx.x * 32 + jl;
    out_img[b * SS + gy * SZ + gx] = acc;
}

// ---------------- launch ----------------
extern "C" void kernel_launch(void* const* d_in, const int* in_sizes, int n_in,
                              void* d_out, int out_size) {
    const float *x_sino = 0, *y_prev = 0, *y_cat = 0, *angles = 0, *step = 0;
    const float *w1 = 0, *b1 = 0, *w2 = 0, *b2 = 0, *w3 = 0, *b3 = 0;

    int ix = -1;
    for (int i = 0; i < n_in; ++i) if (in_sizes[i] == 51200) ix = i;
    bool dict_order = (ix == 0);

    int n262 = 0, n32 = 0, n1 = 0;
    for (int i = 0; i < n_in; ++i) {
        const float* p = (const float*)d_in[i];
        switch (in_sizes[i]) {
            case 51200: x_sino = p; break;
            case 50:    angles = p; break;
            case 576:   w1 = p; break;
            case 9216:  w2 = p; break;
            case 288:   w3 = p; break;
            case 262144:
                if (dict_order) { if (n262 == 0) y_prev = p; else y_cat = p; }
                else            { if (n262 == 0) y_cat  = p; else y_prev = p; }
                ++n262; break;
            case 32:
                if (n32 == 0) b1 = p; else b2 = p;
                ++n32; break;
            case 1:
                if (dict_order) { if (n1 == 0) step = p; else b3 = p; }
                else            { if (n1 == 0) b3   = p; else step = p; }
                ++n1; break;
            default: break;
        }
    }

    float* out_img = (float*)d_out;
    float* out_up;
    if (out_size >= 2 * BB * SS) {
        out_up = (float*)d_out + BB * SS;
    } else {
        cudaGetSymbolAddress((void**)&out_up, g_up);
    }

    k_radon<<<dim3(NA, BB, NZ), 256>>>(y_prev, angles);
    k_filter<<<dim3(NA, BB), 256>>>(x_sino);
    k_backproj<<<dim3(SZ / 4, BB), 1024>>>(y_prev, angles, step, out_up);
    k_conv1<<<dim3(8, 32, BB), 256>>>(out_up, y_cat, w1, b1);
    k_conv2<<<dim3(8, 32, BB), 256>>>(w2, b2);
    k_conv3<<<dim3(8, 32, BB), 256>>>(w3, b3, out_img);
}